// round 16
// baseline (speedup 1.0000x reference)
#include <cuda_runtime.h>
#include <cuda_fp16.h>
#include <cstdint>

#define N_NODES 100000
#define IN_CH   256
#define OUT_CH  128
#define N_EDGES 1600000
#define BUCKET  96
#define FULL_MASK 0xFFFFFFFFu

// ---------------- scratch ----------------
__device__ __align__(16) __half2 g_xph[(size_t)N_NODES * (OUT_CH / 2)]; // fp16 xp
__device__ __align__(16) __half  g_wh[(size_t)OUT_CH * IN_CH];          // W^T fp16 [n][k]
__device__ __align__(16) float   g_ws[IN_CH];   // W @ att_src
__device__ __align__(16) float   g_wd[IN_CH];   // W @ att_dst
__device__ float g_asrc[N_NODES];
__device__ float g_adst[N_NODES];
__device__ int   g_cursor[N_NODES];
__device__ __align__(8) int2 g_csrw[(size_t)N_NODES * BUCKET];  // (src, weight-bits)

// ---------------- helpers ----------------
__device__ __forceinline__ void mma_f16(float* c, const uint32_t* a, const uint32_t* b) {
    asm volatile(
        "mma.sync.aligned.m16n8k16.row.col.f32.f16.f16.f32 "
        "{%0,%1,%2,%3}, {%4,%5,%6,%7}, {%8,%9}, {%0,%1,%2,%3};"
        : "+f"(c[0]), "+f"(c[1]), "+f"(c[2]), "+f"(c[3])
        : "r"(a[0]), "r"(a[1]), "r"(a[2]), "r"(a[3]), "r"(b[0]), "r"(b[1]));
}
__device__ __forceinline__ uint32_t smem_u32(const void* p) {
    uint32_t a;
    asm("{ .reg .u64 t; cvta.to.shared.u64 t, %1; cvt.u32.u64 %0, t; }" : "=r"(a) : "l"(p));
    return a;
}
__device__ __forceinline__ void cp16(uint32_t dst, const void* src) {
    asm volatile("cp.async.cg.shared.global [%0], [%1], 16;"
                 :: "r"(dst), "l"(src) : "memory");
}
#define CP_COMMIT() asm volatile("cp.async.commit_group;" ::: "memory")
#define CP_WAIT0()  asm volatile("cp.async.wait_group 0;" ::: "memory")

// ---------------- init: zero cursors ----------------
__global__ void init_kernel() {
    int i = blockIdx.x * blockDim.x + threadIdx.x;
    if (i < N_NODES) g_cursor[i] = 0;
}

// ---------------- W transpose + fp16 ----------------
__global__ void wh_kernel(const float* __restrict__ W) {
    int i = blockIdx.x * blockDim.x + threadIdx.x;
    if (i >= OUT_CH * IN_CH) return;
    int n = i >> 8;
    int k = i & 255;
    g_wh[(size_t)n * IN_CH + k] = __float2half(W[(size_t)k * OUT_CH + n]);
}

// ---------------- ws/wd: ws[k] = sum_n W[k][n] * att_src[n] ----------------
__global__ void wsd_kernel(const float* __restrict__ W,
                           const float* __restrict__ att_src,
                           const float* __restrict__ att_dst) {
    int k    = (blockIdx.x * blockDim.x + threadIdx.x) >> 5;   // one warp per k
    int lane = threadIdx.x & 31;
    if (k >= IN_CH) return;
    float4 w0 = *(const float4*)&W[(size_t)k * OUT_CH + lane * 4];
    float4 a0 = ((const float4*)att_src)[lane];
    float4 d0 = ((const float4*)att_dst)[lane];
    float ps = w0.x * a0.x + w0.y * a0.y + w0.z * a0.z + w0.w * a0.w;
    float pd = w0.x * d0.x + w0.y * d0.y + w0.z * d0.z + w0.w * d0.w;
#pragma unroll
    for (int off = 16; off; off >>= 1) {
        ps += __shfl_xor_sync(FULL_MASK, ps, off);
        pd += __shfl_xor_sync(FULL_MASK, pd, off);
    }
    if (lane == 0) {
        g_ws[k] = ps;
        g_wd[k] = pd;
    }
}

// ---------------- alpha from x: asrc[i] = x[i]·ws, adst[i] = x[i]·wd ----------------
__global__ void alpha_kernel(const float* __restrict__ X) {
    int gw   = (blockIdx.x * blockDim.x + threadIdx.x) >> 5;   // one warp per node
    int lane = threadIdx.x & 31;
    if (gw >= N_NODES) return;
    const float4* xr = (const float4*)(X + (size_t)gw * IN_CH);
    float ps = 0.f, pd = 0.f;
#pragma unroll
    for (int t = 0; t < 2; t++) {
        int i = lane + t * 32;
        float4 v = xr[i];
        float4 s = ((const float4*)g_ws)[i];
        float4 d = ((const float4*)g_wd)[i];
        ps += v.x * s.x + v.y * s.y + v.z * s.z + v.w * s.w;
        pd += v.x * d.x + v.y * d.y + v.z * d.z + v.w * d.w;
    }
#pragma unroll
    for (int off = 16; off; off >>= 1) {
        ps += __shfl_xor_sync(FULL_MASK, ps, off);
        pd += __shfl_xor_sync(FULL_MASK, pd, off);
    }
    if (lane == 0) {
        g_asrc[gw] = ps;
        g_adst[gw] = pd;
    }
}

// ---------------- GEMM (fp16 mma m16n8k16), plain xp->fp16 epilogue ----------------
#define T_PITCH 40
#define TS_H (128 * T_PITCH)
#define SMEM_BYTES (4 * TS_H * 2)

__global__ void __launch_bounds__(256) gemm_kernel(const float* __restrict__ X) {
    extern __shared__ __half smh[];
    __half* As = smh;
    __half* Bs = smh + 2 * TS_H;

    const int tid    = threadIdx.x;
    const int lane   = tid & 31;
    const int w      = tid >> 5;
    const int warp_m = w & 1;
    const int warp_n = w >> 1;
    const int gid    = lane >> 2;
    const int tig    = lane & 3;
    const int bm     = blockIdx.x * 128;

    const uint32_t smem_base = smem_u32(smh);
    const uint32_t bs_base   = smem_base + 2 * TS_H * 2;

    const int a_row = tid >> 3;
    const int a_kq  = (tid & 7) << 2;
    const int b_row = tid >> 2;
    const int b_k8  = (tid & 3) << 3;

    auto ldb = [&](int kc, int buf) {
#pragma unroll
        for (int t = 0; t < 2; t++) {
            int n = b_row + t * 64;
            uint32_t dst = bs_base + (uint32_t)(buf * TS_H + n * T_PITCH + b_k8) * 2u;
            cp16(dst, &g_wh[(size_t)n * IN_CH + kc * 32 + b_k8]);
        }
        CP_COMMIT();
    };
    auto lda = [&](int kc, float4* v) {
#pragma unroll
        for (int t = 0; t < 4; t++) {
            int row = a_row + t * 32;
            if (bm + row < N_NODES)
                v[t] = *(const float4*)&X[(size_t)(bm + row) * IN_CH + kc * 32 + a_kq];
            else
                v[t] = make_float4(0.f, 0.f, 0.f, 0.f);
        }
    };
    auto sta = [&](int buf, const float4* v) {
        __half* dst = As + buf * TS_H;
#pragma unroll
        for (int t = 0; t < 4; t++) {
            int row = a_row + t * 32;
            __half2 h0 = __floats2half2_rn(v[t].x, v[t].y);
            __half2 h1 = __floats2half2_rn(v[t].z, v[t].w);
            uint2 pk = make_uint2(*(uint32_t*)&h0, *(uint32_t*)&h1);
            *(uint2*)&dst[row * T_PITCH + a_kq] = pk;
        }
    };

    float acc[4][4][4];
#pragma unroll
    for (int mi = 0; mi < 4; mi++)
#pragma unroll
        for (int nj = 0; nj < 4; nj++)
#pragma unroll
            for (int q = 0; q < 4; q++) acc[mi][nj][q] = 0.f;

    ldb(0, 0);
    {
        float4 v[4];
        lda(0, v);
        sta(0, v);
    }
    CP_WAIT0();
    __syncthreads();

    for (int kc = 0; kc < 8; kc++) {
        float4 nx[4];
        if (kc + 1 < 8) {
            ldb(kc + 1, (kc + 1) & 1);
            lda(kc + 1, nx);
        }

        const __half* Asb = As + (kc & 1) * TS_H;
        const __half* Bsb = Bs + (kc & 1) * TS_H;
#pragma unroll
        for (int kb = 0; kb < 2; kb++) {
            const int kk = kb * 16 + 2 * tig;
            uint32_t a[4][4], b[4][2];
#pragma unroll
            for (int mi = 0; mi < 4; mi++) {
                int r = warp_m * 64 + mi * 16 + gid;
                a[mi][0] = *(const uint32_t*)&Asb[r * T_PITCH + kk];
                a[mi][1] = *(const uint32_t*)&Asb[(r + 8) * T_PITCH + kk];
                a[mi][2] = *(const uint32_t*)&Asb[r * T_PITCH + kk + 8];
                a[mi][3] = *(const uint32_t*)&Asb[(r + 8) * T_PITCH + kk + 8];
            }
#pragma unroll
            for (int nj = 0; nj < 4; nj++) {
                int cn = warp_n * 32 + nj * 8 + gid;
                b[nj][0] = *(const uint32_t*)&Bsb[cn * T_PITCH + kk];
                b[nj][1] = *(const uint32_t*)&Bsb[cn * T_PITCH + kk + 8];
            }
#pragma unroll
            for (int mi = 0; mi < 4; mi++)
#pragma unroll
                for (int nj = 0; nj < 4; nj++)
                    mma_f16(acc[mi][nj], a[mi], b[nj]);
        }

        if (kc + 1 < 8) {
            sta((kc + 1) & 1, nx);
            CP_WAIT0();
        }
        __syncthreads();
    }

    // ---- epilogue: fp16 emit only ----
#pragma unroll
    for (int mi = 0; mi < 4; mi++) {
        int r0 = bm + warp_m * 64 + mi * 16 + gid;
        int r1 = r0 + 8;
#pragma unroll
        for (int nj = 0; nj < 4; nj++) {
            int hc = (warp_n * 32 + nj * 8 + 2 * tig) >> 1;
            if (r0 < N_NODES)
                g_xph[(size_t)r0 * (OUT_CH / 2) + hc] =
                    __floats2half2_rn(acc[mi][nj][0], acc[mi][nj][1]);
            if (r1 < N_NODES)
                g_xph[(size_t)r1 * (OUT_CH / 2) + hc] =
                    __floats2half2_rn(acc[mi][nj][2], acc[mi][nj][3]);
        }
    }
}

// ---------------- scatter + weights into fixed-stride buckets ----------------
__device__ __forceinline__ void scat1(int s, int d) {
    if (s != d) {
        float a = g_asrc[s] + g_adst[d];
        a = a > 0.f ? a : 0.2f * a;
        float wv = __expf(a);
        int pos = atomicAdd(&g_cursor[d], 1);
        g_csrw[d * BUCKET + pos] = make_int2(s, __float_as_int(wv));
    }
}
__global__ void scatter_kernel(const int* __restrict__ ei) {
    int t = blockIdx.x * blockDim.x + threadIdx.x;
    if (t >= N_EDGES / 4) return;
    int4 s = ((const int4*)ei)[t];
    int4 d = ((const int4*)(ei + N_EDGES))[t];
    scat1(s.x, d.x);
    scat1(s.y, d.y);
    scat1(s.z, d.z);
    scat1(s.w, d.w);
}

// ---------------- fused softmax + aggregation (precomputed weights) ----------------
__device__ __forceinline__ void acc8(float* acc, float wj, uint4 h) {
    float2 p0 = __half22float2(*(const __half2*)&h.x);
    float2 p1 = __half22float2(*(const __half2*)&h.y);
    float2 p2 = __half22float2(*(const __half2*)&h.z);
    float2 p3 = __half22float2(*(const __half2*)&h.w);
    acc[0] += wj * p0.x;  acc[1] += wj * p0.y;
    acc[2] += wj * p1.x;  acc[3] += wj * p1.y;
    acc[4] += wj * p2.x;  acc[5] += wj * p2.y;
    acc[6] += wj * p3.x;  acc[7] += wj * p3.y;
}

__global__ void __launch_bounds__(256) aggregate_kernel(const float* __restrict__ bias,
                                                        float* __restrict__ out) {
    int gw   = (blockIdx.x * blockDim.x + threadIdx.x) >> 5;
    int lane = threadIdx.x & 31;
    if (gw >= N_NODES) return;

    const int half = lane >> 4;
    const int lc   = lane & 15;

    float a0 = g_asrc[gw] + g_adst[gw];
    a0 = a0 > 0.f ? a0 : 0.2f * a0;
    float w0 = __expf(a0);

    const uint4* xph16 = (const uint4*)g_xph;

    float acc[8];
#pragma unroll
    for (int q = 0; q < 8; q++) acc[q] = 0.f;
    float denom_l = 0.f;

    const int beg = gw * BUCKET;
    const int cnt = g_cursor[gw];

    for (int base = 0; base < cnt; base += 32) {
        int e = base + lane;
        int2 p = make_int2(0, 0);
        if (e < cnt) p = g_csrw[beg + e];
        int   s = p.x;
        float w = __int_as_float(p.y);   // 0.0f for invalid lanes
        denom_l += w;
        int nv = cnt - base;
        if (nv > 32) nv = 32;

        int j = 0;
        for (; j + 8 <= nv; j += 8) {
            int j0 = j + half, j1 = j + 2 + half, j2 = j + 4 + half, j3 = j + 6 + half;
            int   s0 = __shfl_sync(FULL_MASK, s, j0);
            int   s1 = __shfl_sync(FULL_MASK, s, j1);
            int   s2 = __shfl_sync(FULL_MASK, s, j2);
            int   s3 = __shfl_sync(FULL_MASK, s, j3);
            float u0 = __shfl_sync(FULL_MASK, w, j0);
            float u1 = __shfl_sync(FULL_MASK, w, j1);
            float u2 = __shfl_sync(FULL_MASK, w, j2);
            float u3 = __shfl_sync(FULL_MASK, w, j3);
            uint4 h0 = xph16[s0 * 16 + lc];
            uint4 h1 = xph16[s1 * 16 + lc];
            uint4 h2 = xph16[s2 * 16 + lc];
            uint4 h3 = xph16[s3 * 16 + lc];
            acc8(acc, u0, h0);
            acc8(acc, u1, h1);
            acc8(acc, u2, h2);
            acc8(acc, u3, h3);
        }
        for (; j + 4 <= nv; j += 4) {
            int j0 = j + half, j1 = j + 2 + half;
            int   s0 = __shfl_sync(FULL_MASK, s, j0);
            int   s1 = __shfl_sync(FULL_MASK, s, j1);
            float u0 = __shfl_sync(FULL_MASK, w, j0);
            float u1 = __shfl_sync(FULL_MASK, w, j1);
            uint4 h0 = xph16[s0 * 16 + lc];
            uint4 h1 = xph16[s1 * 16 + lc];
            acc8(acc, u0, h0);
            acc8(acc, u1, h1);
        }
        for (; j < nv; j += 2) {
            int jj = j + half;
            int   sj = __shfl_sync(FULL_MASK, s, jj & 31);
            float wj = __shfl_sync(FULL_MASK, w, jj & 31);
            if (jj >= nv) wj = 0.f;
            uint4 h = xph16[sj * 16 + lc];
            acc8(acc, wj, h);
        }
    }

#pragma unroll
    for (int q = 0; q < 8; q++)
        acc[q] += __shfl_xor_sync(FULL_MASK, acc[q], 16);

#pragma unroll
    for (int off = 16; off; off >>= 1)
        denom_l += __shfl_xor_sync(FULL_MASK, denom_l, off);

    if (half == 0) {
        uint4 hs = xph16[gw * 16 + lc];
        acc8(acc, w0, hs);
        float inv = 1.f / (w0 + denom_l + 1e-16f);
        float4 b0 = ((const float4*)bias)[lc * 2];
        float4 b1 = ((const float4*)bias)[lc * 2 + 1];
        float4 o0 = make_float4(acc[0] * inv + b0.x, acc[1] * inv + b0.y,
                                acc[2] * inv + b0.z, acc[3] * inv + b0.w);
        float4 o1 = make_float4(acc[4] * inv + b1.x, acc[5] * inv + b1.y,
                                acc[6] * inv + b1.z, acc[7] * inv + b1.w);
        ((float4*)(out + (size_t)gw * OUT_CH))[lc * 2]     = o0;
        ((float4*)(out + (size_t)gw * OUT_CH))[lc * 2 + 1] = o1;
    }
}

// ---------------- launch: fork/join ----------------
extern "C" void kernel_launch(void* const* d_in, const int* in_sizes, int n_in,
                              void* d_out, int out_size) {
    const float* x       = (const float*)d_in[0];
    const int*   ei      = (const int*)d_in[1];
    const float* W       = (const float*)d_in[2];
    const float* att_src = (const float*)d_in[3];
    const float* att_dst = (const float*)d_in[4];
    const float* bias    = (const float*)d_in[5];
    float*       out     = (float*)d_out;

    (void)in_sizes; (void)n_in; (void)out_size;

    static cudaStream_t sA = nullptr, sB = nullptr;
    static cudaEvent_t  ev0 = nullptr, evA = nullptr, evB = nullptr;
    if (sA == nullptr) {
        cudaStreamCreateWithFlags(&sA, cudaStreamNonBlocking);
        cudaStreamCreateWithFlags(&sB, cudaStreamNonBlocking);
        cudaEventCreateWithFlags(&ev0, cudaEventDisableTiming);
        cudaEventCreateWithFlags(&evA, cudaEventDisableTiming);
        cudaEventCreateWithFlags(&evB, cudaEventDisableTiming);
        cudaFuncSetAttribute(gemm_kernel, cudaFuncAttributeMaxDynamicSharedMemorySize,
                             SMEM_BYTES);
    }

    // fork
    cudaEventRecord(ev0, 0);
    cudaStreamWaitEvent(sA, ev0, 0);
    cudaStreamWaitEvent(sB, ev0, 0);

    // branch A: W->fp16 transpose, then GEMM (xp fp16 emit only)
    wh_kernel<<<(OUT_CH * IN_CH + 255) / 256, 256, 0, sA>>>(W);
    gemm_kernel<<<(N_NODES + 127) / 128, 256, SMEM_BYTES, sA>>>(x);

    // branch B: ws/wd -> alpha from x -> init -> scatter with weights
    wsd_kernel<<<(IN_CH * 32 + 255) / 256, 256, 0, sB>>>(W, att_src, att_dst);
    alpha_kernel<<<(N_NODES * 32 + 255) / 256, 256, 0, sB>>>(x);
    init_kernel<<<(N_NODES + 1023) / 1024, 1024, 0, sB>>>();
    scatter_kernel<<<(N_EDGES / 4 + 255) / 256, 256, 0, sB>>>(ei);

    // join
    cudaEventRecord(evA, sA);
    cudaEventRecord(evB, sB);
    cudaStreamWaitEvent(0, evA, 0);
    cudaStreamWaitEvent(0, evB, 0);

    aggregate_kernel<<<(N_NODES * 32 + 255) / 256, 256>>>(bias, out);
}

// round 17
// speedup vs baseline: 1.1448x; 1.1448x over previous
#include <cuda_runtime.h>
#include <cuda_fp16.h>
#include <cstdint>

#define N_NODES 100000
#define IN_CH   256
#define OUT_CH  128
#define N_EDGES 1600000
#define BUCKET  96
#define FULL_MASK 0xFFFFFFFFu

// ---------------- scratch ----------------
__device__ __align__(16) __half2 g_xph[(size_t)N_NODES * (OUT_CH / 2)]; // fp16 xp
__device__ __align__(16) __half  g_wh[(size_t)OUT_CH * IN_CH];          // W^T fp16 [n][k]
__device__ float g_asrc[N_NODES];
__device__ float g_adst[N_NODES];
__device__ int   g_cursor[N_NODES];
__device__ int   g_csr[(size_t)N_NODES * BUCKET];

// ---------------- helpers ----------------
__device__ __forceinline__ void mma_f16(float* c, const uint32_t* a, const uint32_t* b) {
    asm volatile(
        "mma.sync.aligned.m16n8k16.row.col.f32.f16.f16.f32 "
        "{%0,%1,%2,%3}, {%4,%5,%6,%7}, {%8,%9}, {%0,%1,%2,%3};"
        : "+f"(c[0]), "+f"(c[1]), "+f"(c[2]), "+f"(c[3])
        : "r"(a[0]), "r"(a[1]), "r"(a[2]), "r"(a[3]), "r"(b[0]), "r"(b[1]));
}
__device__ __forceinline__ uint32_t smem_u32(const void* p) {
    uint32_t a;
    asm("{ .reg .u64 t; cvta.to.shared.u64 t, %1; cvt.u32.u64 %0, t; }" : "=r"(a) : "l"(p));
    return a;
}
__device__ __forceinline__ void cp16(uint32_t dst, const void* src) {
    asm volatile("cp.async.cg.shared.global [%0], [%1], 16;"
                 :: "r"(dst), "l"(src) : "memory");
}
#define CP_COMMIT() asm volatile("cp.async.commit_group;" ::: "memory")
#define CP_WAIT0()  asm volatile("cp.async.wait_group 0;" ::: "memory")

// ---------------- init: zero cursors ----------------
__global__ void init_kernel() {
    int i = blockIdx.x * blockDim.x + threadIdx.x;
    if (i < N_NODES) g_cursor[i] = 0;
}

// ---------------- W transpose + fp16 ----------------
__global__ void wh_kernel(const float* __restrict__ W) {
    int i = blockIdx.x * blockDim.x + threadIdx.x;
    if (i >= OUT_CH * IN_CH) return;
    int n = i >> 8;
    int k = i & 255;
    g_wh[(size_t)n * IN_CH + k] = __float2half(W[(size_t)k * OUT_CH + n]);
}

// ---------------- GEMM: 64x128 CTA tile (3 CTAs/SM), fp16 mma + fused alpha ----------------
// 8 warps, each covers all 64 M rows x 16 N cols (warp_n = w).
#define T_PITCH 40
#define AS_H (64 * T_PITCH)      // per A buffer (halves)
#define BS_H (128 * T_PITCH)     // per B buffer (halves)
#define SMEM_BYTES ((2 * AS_H + 2 * BS_H) * 2)

__global__ void __launch_bounds__(256) gemm_kernel(const float* __restrict__ X,
                                                   const float* __restrict__ att_src,
                                                   const float* __restrict__ att_dst) {
    extern __shared__ __half smh[];
    __half* As = smh;                 // 2 x [64][T_PITCH]
    __half* Bs = smh + 2 * AS_H;      // 2 x [128][T_PITCH]
    __shared__ float s_a[128];        // 64 rows x {ps, pd}

    const int tid    = threadIdx.x;
    const int lane   = tid & 31;
    const int warp_n = tid >> 5;      // 0..7
    const int gid    = lane >> 2;
    const int tig    = lane & 3;
    const int bm     = blockIdx.x * 64;

    const uint32_t smem_base = smem_u32(smh);
    const uint32_t bs_base   = smem_base + 2 * AS_H * 2;

    // A: 64 rows x 32 k fp32 = 512 float4, 2/thread
    const int a_row = tid >> 3;               // 0..31, +32 on t=1
    const int a_kq  = (tid & 7) << 2;
    // B: 128 n x 32 k halves = 512 x 8-half chunks, 2/thread
    const int b_row = tid >> 2;               // 0..63, +64 on t=1
    const int b_k8  = (tid & 3) << 3;

    auto ldb = [&](int kc, int buf) {
#pragma unroll
        for (int t = 0; t < 2; t++) {
            int n = b_row + t * 64;
            uint32_t dst = bs_base + (uint32_t)(buf * BS_H + n * T_PITCH + b_k8) * 2u;
            cp16(dst, &g_wh[(size_t)n * IN_CH + kc * 32 + b_k8]);
        }
        CP_COMMIT();
    };
    auto lda = [&](int kc, float4* v) {
#pragma unroll
        for (int t = 0; t < 2; t++) {
            int row = a_row + t * 32;
            if (bm + row < N_NODES)
                v[t] = *(const float4*)&X[(size_t)(bm + row) * IN_CH + kc * 32 + a_kq];
            else
                v[t] = make_float4(0.f, 0.f, 0.f, 0.f);
        }
    };
    auto sta = [&](int buf, const float4* v) {
        __half* dst = As + buf * AS_H;
#pragma unroll
        for (int t = 0; t < 2; t++) {
            int row = a_row + t * 32;
            __half2 h0 = __floats2half2_rn(v[t].x, v[t].y);
            __half2 h1 = __floats2half2_rn(v[t].z, v[t].w);
            uint2 pk = make_uint2(*(uint32_t*)&h0, *(uint32_t*)&h1);
            *(uint2*)&dst[row * T_PITCH + a_kq] = pk;
        }
    };

    float acc[4][2][4];
#pragma unroll
    for (int mi = 0; mi < 4; mi++)
#pragma unroll
        for (int nj = 0; nj < 2; nj++)
#pragma unroll
            for (int q = 0; q < 4; q++) acc[mi][nj][q] = 0.f;

    ldb(0, 0);
    {
        float4 v[2];
        lda(0, v);
        sta(0, v);
    }
    CP_WAIT0();
    __syncthreads();

    for (int kc = 0; kc < 8; kc++) {
        float4 nx[2];
        if (kc + 1 < 8) {
            ldb(kc + 1, (kc + 1) & 1);
            lda(kc + 1, nx);
        }

        const __half* Asb = As + (kc & 1) * AS_H;
        const __half* Bsb = Bs + (kc & 1) * BS_H;
#pragma unroll
        for (int kb = 0; kb < 2; kb++) {
            const int kk = kb * 16 + 2 * tig;
            uint32_t a[4][4], b[2][2];
#pragma unroll
            for (int mi = 0; mi < 4; mi++) {
                int r = mi * 16 + gid;
                a[mi][0] = *(const uint32_t*)&Asb[r * T_PITCH + kk];
                a[mi][1] = *(const uint32_t*)&Asb[(r + 8) * T_PITCH + kk];
                a[mi][2] = *(const uint32_t*)&Asb[r * T_PITCH + kk + 8];
                a[mi][3] = *(const uint32_t*)&Asb[(r + 8) * T_PITCH + kk + 8];
            }
#pragma unroll
            for (int nj = 0; nj < 2; nj++) {
                int cn = warp_n * 16 + nj * 8 + gid;
                b[nj][0] = *(const uint32_t*)&Bsb[cn * T_PITCH + kk];
                b[nj][1] = *(const uint32_t*)&Bsb[cn * T_PITCH + kk + 8];
            }
#pragma unroll
            for (int mi = 0; mi < 4; mi++)
#pragma unroll
                for (int nj = 0; nj < 2; nj++)
                    mma_f16(acc[mi][nj], a[mi], b[nj]);
        }

        if (kc + 1 < 8) {
            sta((kc + 1) & 1, nx);
            CP_WAIT0();
        }
        __syncthreads();
    }

    // ---- epilogue: fp16 emit + fused alpha (smem reduce over 8 warp columns) ----
    if (tid < 128) s_a[tid] = 0.f;
    __syncthreads();

    float asv[2][2], adv[2][2];
#pragma unroll
    for (int nj = 0; nj < 2; nj++) {
        int c = warp_n * 16 + nj * 8 + 2 * tig;
        asv[nj][0] = __ldg(&att_src[c]);
        asv[nj][1] = __ldg(&att_src[c + 1]);
        adv[nj][0] = __ldg(&att_dst[c]);
        adv[nj][1] = __ldg(&att_dst[c + 1]);
    }

#pragma unroll
    for (int mi = 0; mi < 4; mi++) {
        int lr0 = mi * 16 + gid;
        int lr1 = lr0 + 8;
        int r0 = bm + lr0;
        int r1 = bm + lr1;
        float ps0 = 0.f, pd0 = 0.f, ps1 = 0.f, pd1 = 0.f;
#pragma unroll
        for (int nj = 0; nj < 2; nj++) {
            int c  = warp_n * 16 + nj * 8 + 2 * tig;
            int hc = c >> 1;
            float2 v0 = make_float2(acc[mi][nj][0], acc[mi][nj][1]);
            float2 v1 = make_float2(acc[mi][nj][2], acc[mi][nj][3]);
            if (r0 < N_NODES)
                g_xph[(size_t)r0 * (OUT_CH / 2) + hc] = __floats2half2_rn(v0.x, v0.y);
            if (r1 < N_NODES)
                g_xph[(size_t)r1 * (OUT_CH / 2) + hc] = __floats2half2_rn(v1.x, v1.y);
            ps0 += v0.x * asv[nj][0] + v0.y * asv[nj][1];
            pd0 += v0.x * adv[nj][0] + v0.y * adv[nj][1];
            ps1 += v1.x * asv[nj][0] + v1.y * asv[nj][1];
            pd1 += v1.x * adv[nj][0] + v1.y * adv[nj][1];
        }
#pragma unroll
        for (int off = 1; off < 4; off <<= 1) {
            ps0 += __shfl_xor_sync(FULL_MASK, ps0, off);
            pd0 += __shfl_xor_sync(FULL_MASK, pd0, off);
            ps1 += __shfl_xor_sync(FULL_MASK, ps1, off);
            pd1 += __shfl_xor_sync(FULL_MASK, pd1, off);
        }
        if (tig == 0) {
            atomicAdd(&s_a[lr0 * 2 + 0], ps0);
            atomicAdd(&s_a[lr0 * 2 + 1], pd0);
            atomicAdd(&s_a[lr1 * 2 + 0], ps1);
            atomicAdd(&s_a[lr1 * 2 + 1], pd1);
        }
    }
    __syncthreads();

    if (tid < 64) {
        int r = bm + tid;
        if (r < N_NODES) {
            g_asrc[r] = s_a[tid * 2 + 0];
            g_adst[r] = s_a[tid * 2 + 1];
        }
    }
}

// ---------------- scatter into fixed-stride buckets, 2 edges/thread ----------------
__device__ __forceinline__ void scat1(int s, int d) {
    if (s != d) {
        int pos = atomicAdd(&g_cursor[d], 1);
        g_csr[d * BUCKET + pos] = s;
    }
}
__global__ void scatter_kernel(const int* __restrict__ ei) {
    int t = blockIdx.x * blockDim.x + threadIdx.x;
    if (t >= N_EDGES / 2) return;
    int2 s = ((const int2*)ei)[t];
    int2 d = ((const int2*)(ei + N_EDGES))[t];
    scat1(s.x, d.x);
    scat1(s.y, d.y);
}

// ---------------- fused softmax + aggregation (R13/R15 config) ----------------
__device__ __forceinline__ void acc8(float* acc, float wj, uint4 h) {
    float2 p0 = __half22float2(*(const __half2*)&h.x);
    float2 p1 = __half22float2(*(const __half2*)&h.y);
    float2 p2 = __half22float2(*(const __half2*)&h.z);
    float2 p3 = __half22float2(*(const __half2*)&h.w);
    acc[0] += wj * p0.x;  acc[1] += wj * p0.y;
    acc[2] += wj * p1.x;  acc[3] += wj * p1.y;
    acc[4] += wj * p2.x;  acc[5] += wj * p2.y;
    acc[6] += wj * p3.x;  acc[7] += wj * p3.y;
}

__global__ void __launch_bounds__(256) aggregate_kernel(const float* __restrict__ bias,
                                                        float* __restrict__ out) {
    int gw   = (blockIdx.x * blockDim.x + threadIdx.x) >> 5;
    int lane = threadIdx.x & 31;
    if (gw >= N_NODES) return;

    const int half = lane >> 4;
    const int lc   = lane & 15;

    float adi = g_adst[gw];
    float a0 = g_asrc[gw] + adi;
    a0 = a0 > 0.f ? a0 : 0.2f * a0;
    float w0 = __expf(a0);

    const uint4* xph16 = (const uint4*)g_xph;

    float acc[8];
#pragma unroll
    for (int q = 0; q < 8; q++) acc[q] = 0.f;
    float denom_l = 0.f;

    const int beg = gw * BUCKET;
    const int cnt = g_cursor[gw];

    for (int base = 0; base < cnt; base += 32) {
        int e = base + lane;
        int s = 0;
        float w = 0.f;
        if (e < cnt) {
            s = g_csr[beg + e];
            float a = g_asrc[s] + adi;
            a = a > 0.f ? a : 0.2f * a;
            w = __expf(a);
        }
        denom_l += w;
        int nv = cnt - base;
        if (nv > 32) nv = 32;

        int j = 0;
        for (; j + 8 <= nv; j += 8) {
            int j0 = j + half, j1 = j + 2 + half, j2 = j + 4 + half, j3 = j + 6 + half;
            int   s0 = __shfl_sync(FULL_MASK, s, j0);
            int   s1 = __shfl_sync(FULL_MASK, s, j1);
            int   s2 = __shfl_sync(FULL_MASK, s, j2);
            int   s3 = __shfl_sync(FULL_MASK, s, j3);
            float u0 = __shfl_sync(FULL_MASK, w, j0);
            float u1 = __shfl_sync(FULL_MASK, w, j1);
            float u2 = __shfl_sync(FULL_MASK, w, j2);
            float u3 = __shfl_sync(FULL_MASK, w, j3);
            uint4 h0 = xph16[s0 * 16 + lc];
            uint4 h1 = xph16[s1 * 16 + lc];
            uint4 h2 = xph16[s2 * 16 + lc];
            uint4 h3 = xph16[s3 * 16 + lc];
            acc8(acc, u0, h0);
            acc8(acc, u1, h1);
            acc8(acc, u2, h2);
            acc8(acc, u3, h3);
        }
        for (; j + 4 <= nv; j += 4) {
            int j0 = j + half, j1 = j + 2 + half;
            int   s0 = __shfl_sync(FULL_MASK, s, j0);
            int   s1 = __shfl_sync(FULL_MASK, s, j1);
            float u0 = __shfl_sync(FULL_MASK, w, j0);
            float u1 = __shfl_sync(FULL_MASK, w, j1);
            uint4 h0 = xph16[s0 * 16 + lc];
            uint4 h1 = xph16[s1 * 16 + lc];
            acc8(acc, u0, h0);
            acc8(acc, u1, h1);
        }
        for (; j < nv; j += 2) {
            int jj = j + half;
            int   sj = __shfl_sync(FULL_MASK, s, jj & 31);
            float wj = __shfl_sync(FULL_MASK, w, jj & 31);
            if (jj >= nv) wj = 0.f;
            uint4 h = xph16[sj * 16 + lc];
            acc8(acc, wj, h);
        }
    }

#pragma unroll
    for (int q = 0; q < 8; q++)
        acc[q] += __shfl_xor_sync(FULL_MASK, acc[q], 16);

#pragma unroll
    for (int off = 16; off; off >>= 1)
        denom_l += __shfl_xor_sync(FULL_MASK, denom_l, off);

    if (half == 0) {
        uint4 hs = xph16[gw * 16 + lc];
        acc8(acc, w0, hs);
        float inv = 1.f / (w0 + denom_l + 1e-16f);
        float4 b0 = ((const float4*)bias)[lc * 2];
        float4 b1 = ((const float4*)bias)[lc * 2 + 1];
        float4 o0 = make_float4(acc[0] * inv + b0.x, acc[1] * inv + b0.y,
                                acc[2] * inv + b0.z, acc[3] * inv + b0.w);
        float4 o1 = make_float4(acc[4] * inv + b1.x, acc[5] * inv + b1.y,
                                acc[6] * inv + b1.z, acc[7] * inv + b1.w);
        ((float4*)(out + (size_t)gw * OUT_CH))[lc * 2]     = o0;
        ((float4*)(out + (size_t)gw * OUT_CH))[lc * 2 + 1] = o1;
    }
}

// ---------------- launch: fork/join ----------------
extern "C" void kernel_launch(void* const* d_in, const int* in_sizes, int n_in,
                              void* d_out, int out_size) {
    const float* x       = (const float*)d_in[0];
    const int*   ei      = (const int*)d_in[1];
    const float* W       = (const float*)d_in[2];
    const float* att_src = (const float*)d_in[3];
    const float* att_dst = (const float*)d_in[4];
    const float* bias    = (const float*)d_in[5];
    float*       out     = (float*)d_out;

    (void)in_sizes; (void)n_in; (void)out_size;

    static cudaStream_t sA = nullptr, sB = nullptr;
    static cudaEvent_t  ev0 = nullptr, evA = nullptr, evB = nullptr;
    if (sA == nullptr) {
        cudaStreamCreateWithFlags(&sA, cudaStreamNonBlocking);
        cudaStreamCreateWithFlags(&sB, cudaStreamNonBlocking);
        cudaEventCreateWithFlags(&ev0, cudaEventDisableTiming);
        cudaEventCreateWithFlags(&evA, cudaEventDisableTiming);
        cudaEventCreateWithFlags(&evB, cudaEventDisableTiming);
        cudaFuncSetAttribute(gemm_kernel, cudaFuncAttributeMaxDynamicSharedMemorySize,
                             SMEM_BYTES);
    }

    // fork
    cudaEventRecord(ev0, 0);
    cudaStreamWaitEvent(sA, ev0, 0);
    cudaStreamWaitEvent(sB, ev0, 0);

    // branch A: W->fp16 transpose, then 64x128-tile GEMM + fused alpha
    wh_kernel<<<(OUT_CH * IN_CH + 255) / 256, 256, 0, sA>>>(W);
    gemm_kernel<<<(N_NODES + 63) / 64, 256, SMEM_BYTES, sA>>>(x, att_src, att_dst);

    // branch B: bucket CSR build
    init_kernel<<<(N_NODES + 1023) / 1024, 1024, 0, sB>>>();
    scatter_kernel<<<(N_EDGES / 2 + 255) / 256, 256, 0, sB>>>(ei);

    // join
    cudaEventRecord(evA, sA);
    cudaEventRecord(evB, sB);
    cudaStreamWaitEvent(0, evA, 0);
    cudaStreamWaitEvent(0, evB, 0);

    aggregate_kernel<<<(N_NODES * 32 + 255) / 256, 256>>>(bias, out);
}